// round 15
// baseline (speedup 1.0000x reference)
#include <cuda_runtime.h>
#include <cuda_bf16.h>

// MomentumLSTM v14: fully rotated pipeline — every MUFU (pointwise) region fused
// into an FMA region:
//   step t: [L1-h gates] sync [pw-L1 || L2-rec || x-store/LDG] sync
//           [L2-input; pw-L2 || L1-x(t+1) from double-buffered x slab] sync
// Plus pre-duplicated biases in SMEM (init = 8 broadcast LDS.64, zero MOVs).
// Base: v13 (2073us), 512 thr, 128 regs, warp-local recurrence.

#define BATCH  32768
#define TT     60
#define DD     7
#define H1     64
#define G1     256
#define H2     32
#define G2     128
#define NT     512
#define GRID   152
#define TB     8                 // batches per warp-task
#define NTASKS (BATCH / TB)      // 4096
#define WSLOTS (GRID * 16)       // 2432
#define HS1    10                // even stride: [64][10] per-warp h1 slab
#define HS2    10                // [32][10]
#define XS     8                 // [7][8] per x buffer

// SMEM float offsets
#define OFF_W1T 0                // [71][256] rows 0..6 x-w, 7..70 h-w (i/f/o pre-scaled 0.5)
#define OFF_W2T 18176            // [96][128]
#define OFF_B1D 30464            // [512] duplicated (b,b) pairs, layout [g*H1+u]*2
#define OFF_B2D 30976            // [256] duplicated
#define OFF_H1  31232            // 16 x 640
#define OFF_H2  41472            // 16 x 320
#define OFF_X   46592            // 16 x 128 (double-buffered [2][7][8])
#define SMEM_FLOATS 48640
#define SMEM_BYTES  (SMEM_FLOATS * 4)   // 194560

typedef unsigned long long u64t;

__device__ __forceinline__ u64t pk2(float a, float b) {
    u64t r; asm("mov.b64 %0, {%1, %2};" : "=l"(r) : "f"(a), "f"(b)); return r;
}
__device__ __forceinline__ void upk(u64t v, float& lo, float& hi) {
    asm("mov.b64 {%0, %1}, %2;" : "=f"(lo), "=f"(hi) : "l"(v));
}
__device__ __forceinline__ u64t fma2(u64t a, u64t b, u64t c) {
    u64t d; asm("fma.rn.f32x2 %0, %1, %2, %3;" : "=l"(d) : "l"(a), "l"(b), "l"(c)); return d;
}
__device__ __forceinline__ u64t lds64(const float* p) {
    return *reinterpret_cast<const u64t*>(p);
}
__device__ __forceinline__ void sts64(float* p, u64t v) {
    *reinterpret_cast<u64t*>(p) = v;
}
__device__ __forceinline__ float tanha(float x) {
    float y; asm("tanh.approx.f32 %0, %1;" : "=f"(y) : "f"(x)); return y;
}
// acc already holds x/2 (weights pre-scaled): sigmoid(x) = 0.5*tanh(x/2)+0.5
__device__ __forceinline__ float sig_h(float halfx) {
    return fmaf(0.5f, tanha(halfx), 0.5f);
}
__device__ __forceinline__ float sigx(float x) {   // exact, output only
    return __fdividef(1.0f, 1.0f + __expf(-x));
}

__global__ void __launch_bounds__(NT, 1)
momentum_lstm_kernel(const float* __restrict__ x,
                     const float* __restrict__ Wih1, const float* __restrict__ Whh1,
                     const float* __restrict__ bih1, const float* __restrict__ bhh1,
                     const float* __restrict__ Wih2, const float* __restrict__ Whh2,
                     const float* __restrict__ bih2, const float* __restrict__ bhh2,
                     const float* __restrict__ Wd,  const float* __restrict__ bd,
                     const float* __restrict__ Wo,  const float* __restrict__ bo,
                     float* __restrict__ out)
{
    extern __shared__ float sm[];
    float* sW1T = sm + OFF_W1T;
    float* sW2T = sm + OFF_W2T;
    float* sB1d = sm + OFF_B1D;
    float* sB2d = sm + OFF_B2D;

    const int tid  = threadIdx.x;
    const int lane = tid & 31;
    const int wid  = tid >> 5;

    float* sH1w = sm + OFF_H1 + wid * (H1 * HS1);
    float* sH2w = sm + OFF_H2 + wid * (H2 * HS2);
    float* sXw  = sm + OFF_X  + wid * 128;

    // ---------------- staging: transpose + pre-scale i/f/o rows by 0.5 ----------------
    for (int i = tid; i < DD * G1; i += NT) {
        int d = i >> 8, g = i & 255;
        float s = ((g >> 6) == 2) ? 1.0f : 0.5f;       // gate order i,f,g,o
        sW1T[d * G1 + g] = s * Wih1[g * DD + d];
    }
    for (int i = tid; i < H1 * G1; i += NT) {
        int k = i >> 8, g = i & 255;
        float s = ((g >> 6) == 2) ? 1.0f : 0.5f;
        sW1T[(DD + k) * G1 + g] = s * Whh1[g * H1 + k];
    }
    for (int i = tid; i < (H1 + H2) * G2; i += NT) {
        int k = i >> 7, g = i & 127;
        float s = ((g >> 5) == 2) ? 1.0f : 0.5f;
        sW2T[i] = s * ((k < H1) ? Wih2[g * H1 + k] : Whh2[g * H2 + (k - H1)]);
    }
    if (tid < G1) {
        float s = ((tid >> 6) == 2) ? 1.0f : 0.5f;
        float b = s * (bih1[tid] + bhh1[tid]);
        sB1d[2 * tid] = b; sB1d[2 * tid + 1] = b;      // duplicated pair
    }
    if (tid < G2) {
        float s = ((tid >> 5) == 2) ? 1.0f : 0.5f;
        float b = s * (bih2[tid] + bhh2[tid]);
        sB2d[2 * tid] = b; sB2d[2 * tid + 1] = b;
    }
    __syncthreads();

    // ---------------- warp-local tilings ----------------
    const int u01 = 2 * lane;               // layer1: lanes span 64 units
    const int u02 = 2 * (lane & 15);        // layer2: 16 lanes span 32 units
    const int bh2 = (lane >> 4) * 4;        // layer2: half-warp batch split (4 each)

    const int gw = wid * GRID + blockIdx.x;   // interleaved task id

    for (int tau = gw; tau < NTASKS; tau += WSLOTS) {
        const float* xg = x + (size_t)tau * TB * (TT * DD);

        // zero h2 slab (L2-recurrent loop is branch-free, reads zeros at t=0)
        for (int i = lane; i < H2 * HS2; i += 32) sH2w[i] = 0.0f;

        float c1[2][TB];
        #pragma unroll
        for (int u = 0; u < 2; u++)
            #pragma unroll
            for (int b = 0; b < TB; b++) c1[u][b] = 0.0f;
        float c2[2][4];
        #pragma unroll
        for (int u = 0; u < 2; u++)
            #pragma unroll
            for (int b = 0; b < 4; b++) c2[u][b] = 0.0f;

        // -------- prologue: x(0) -> buf0, a1 = bias + Wih1*x(0), prefetch x(1) --------
        float xr[2];
        #pragma unroll
        for (int j = 0; j < 2; j++) {
            int idx = 32 * j + lane;
            if (idx < DD * TB) {
                int b = idx / DD, d = idx - b * DD;
                xr[j] = xg[b * (TT * DD) + d];
                sXw[d * XS + b] = xr[j];               // buf0
            }
        }
        __syncwarp();

        u64t a1[2][4][4];
        #pragma unroll
        for (int g = 0; g < 4; g++) {
            u64t plo = lds64(&sB1d[2 * (g * H1 + u01)]);
            u64t phi = lds64(&sB1d[2 * (g * H1 + u01 + 1)]);
            #pragma unroll
            for (int p = 0; p < 4; p++) { a1[0][g][p] = plo; a1[1][g][p] = phi; }
        }
        #pragma unroll
        for (int d = 0; d < DD; d++) {
            u64t wp[2][4];
            #pragma unroll
            for (int g = 0; g < 4; g++) {
                u64t wv = lds64(&sW1T[d * G1 + g * H1 + u01]);
                float wl, wh; upk(wv, wl, wh);
                wp[0][g] = pk2(wl, wl); wp[1][g] = pk2(wh, wh);
            }
            #pragma unroll
            for (int p = 0; p < 4; p++) {
                u64t xv = lds64(&sXw[d * XS + 2 * p]);
                #pragma unroll
                for (int g = 0; g < 4; g++) {
                    a1[0][g][p] = fma2(wp[0][g], xv, a1[0][g][p]);
                    a1[1][g][p] = fma2(wp[1][g], xv, a1[1][g][p]);
                }
            }
        }
        // prefetch x(1)
        #pragma unroll
        for (int j = 0; j < 2; j++) {
            int idx = 32 * j + lane;
            if (idx < DD * TB) {
                int b = idx / DD, d = idx - b * DD;
                xr[j] = xg[b * (TT * DD) + 1 * DD + d];
            }
        }

        for (int t = 0; t < TT; t++) {
            // ================= layer 1 recurrent gates (a1 += Whh1*h1(t-1)) =========
            if (t) {
                #pragma unroll 2
                for (int k = 0; k < H1; k++) {
                    u64t wp[2][4];
                    #pragma unroll
                    for (int g = 0; g < 4; g++) {
                        u64t wv = lds64(&sW1T[(DD + k) * G1 + g * H1 + u01]);
                        float wl, wh; upk(wv, wl, wh);
                        wp[0][g] = pk2(wl, wl); wp[1][g] = pk2(wh, wh);
                    }
                    #pragma unroll
                    for (int p = 0; p < 4; p++) {
                        u64t hv = lds64(&sH1w[k * HS1 + 2 * p]);
                        #pragma unroll
                        for (int g = 0; g < 4; g++) {
                            a1[0][g][p] = fma2(wp[0][g], hv, a1[0][g][p]);
                            a1[1][g][p] = fma2(wp[1][g], hv, a1[1][g][p]);
                        }
                    }
                }
            }
            __syncwarp();                      // WAR on old h1

            // ==== FUSED A: pointwise-L1 (MUFU) || L2-recurrent (FMA) || x staging ====
            u64t a2[2][4][2];
            #pragma unroll
            for (int g = 0; g < 4; g++) {
                u64t plo = lds64(&sB2d[2 * (g * H2 + u02)]);
                u64t phi = lds64(&sB2d[2 * (g * H2 + u02 + 1)]);
                #pragma unroll
                for (int p = 0; p < 2; p++) { a2[0][g][p] = plo; a2[1][g][p] = phi; }
            }
            // x(t+1) -> buf[(t+1)&1]; prefetch x(t+2)
            {
                float* bufn = sXw + ((t + 1) & 1) * 64;
                #pragma unroll
                for (int j = 0; j < 2; j++) {
                    int idx = 32 * j + lane;
                    if (idx < DD * TB) {
                        int b = idx / DD, d = idx - b * DD;
                        bufn[d * XS + b] = xr[j];
                        if (t + 2 < TT)
                            xr[j] = xg[b * (TT * DD) + (t + 2) * DD + d];
                    }
                }
            }
            // pointwise layer1 + write new h1 (MUFU-heavy)
            #pragma unroll
            for (int u = 0; u < 2; u++) {
                #pragma unroll
                for (int p = 0; p < 4; p++) {
                    float gi[2], gf[2], gg[2], go[2], hh[2];
                    upk(a1[u][0][p], gi[0], gi[1]);
                    upk(a1[u][1][p], gf[0], gf[1]);
                    upk(a1[u][2][p], gg[0], gg[1]);
                    upk(a1[u][3][p], go[0], go[1]);
                    #pragma unroll
                    for (int s = 0; s < 2; s++) {
                        float ii = sig_h(gi[s]);
                        float ff = sig_h(gf[s]);
                        float g_ = tanha(gg[s]);
                        float oo = sig_h(go[s]);
                        float cc = ff * c1[u][2 * p + s] + ii * g_;
                        c1[u][2 * p + s] = cc;
                        hh[s] = oo * tanha(cc);
                    }
                    sts64(&sH1w[(u01 + u) * HS1 + 2 * p], pk2(hh[0], hh[1]));
                }
            }
            // layer2 recurrent gates (reads OLD h2) — branch-free, interleaves above
            #pragma unroll 4
            for (int k = 0; k < H2; k++) {
                u64t wp[2][4];
                #pragma unroll
                for (int g = 0; g < 4; g++) {
                    u64t wv = lds64(&sW2T[(H1 + k) * G2 + g * H2 + u02]);
                    float wl, wh; upk(wv, wl, wh);
                    wp[0][g] = pk2(wl, wl); wp[1][g] = pk2(wh, wh);
                }
                #pragma unroll
                for (int p = 0; p < 2; p++) {
                    u64t hv = lds64(&sH2w[k * HS2 + bh2 + 2 * p]);
                    #pragma unroll
                    for (int g = 0; g < 4; g++) {
                        a2[0][g][p] = fma2(wp[0][g], hv, a2[0][g][p]);
                        a2[1][g][p] = fma2(wp[1][g], hv, a2[1][g][p]);
                    }
                }
            }
            __syncwarp();    // h1 RAW; old-h2 WAR; x buf RAW

            // ================= layer2 input gates (new h1) =================
            #pragma unroll 4
            for (int k = 0; k < H1; k++) {
                u64t wp[2][4];
                #pragma unroll
                for (int g = 0; g < 4; g++) {
                    u64t wv = lds64(&sW2T[k * G2 + g * H2 + u02]);
                    float wl, wh; upk(wv, wl, wh);
                    wp[0][g] = pk2(wl, wl); wp[1][g] = pk2(wh, wh);
                }
                #pragma unroll
                for (int p = 0; p < 2; p++) {
                    u64t hv = lds64(&sH1w[k * HS1 + bh2 + 2 * p]);
                    #pragma unroll
                    for (int g = 0; g < 4; g++) {
                        a2[0][g][p] = fma2(wp[0][g], hv, a2[0][g][p]);
                        a2[1][g][p] = fma2(wp[1][g], hv, a2[1][g][p]);
                    }
                }
            }

            // ==== FUSED B: pointwise-L2 (MUFU) || L1-x projection for t+1 (FMA) ====
            // pointwise layer2 + write new h2
            #pragma unroll
            for (int u = 0; u < 2; u++) {
                #pragma unroll
                for (int p = 0; p < 2; p++) {
                    float gi[2], gf[2], gg[2], go[2], hh[2];
                    upk(a2[u][0][p], gi[0], gi[1]);
                    upk(a2[u][1][p], gf[0], gf[1]);
                    upk(a2[u][2][p], gg[0], gg[1]);
                    upk(a2[u][3][p], go[0], go[1]);
                    #pragma unroll
                    for (int s = 0; s < 2; s++) {
                        float ii = sig_h(gi[s]);
                        float ff = sig_h(gf[s]);
                        float g_ = tanha(gg[s]);
                        float oo = sig_h(go[s]);
                        float cc = ff * c2[u][2 * p + s] + ii * g_;
                        c2[u][2 * p + s] = cc;
                        hh[s] = oo * tanha(cc);
                    }
                    sts64(&sH2w[(u02 + u) * HS2 + bh2 + 2 * p], pk2(hh[0], hh[1]));
                }
            }
            // a1(t+1) = bias + Wih1 * x(t+1)  (reads buf[(t+1)&1]; wasted at t=TT-1)
            #pragma unroll
            for (int g = 0; g < 4; g++) {
                u64t plo = lds64(&sB1d[2 * (g * H1 + u01)]);
                u64t phi = lds64(&sB1d[2 * (g * H1 + u01 + 1)]);
                #pragma unroll
                for (int p = 0; p < 4; p++) { a1[0][g][p] = plo; a1[1][g][p] = phi; }
            }
            {
                const float* bufn = sXw + ((t + 1) & 1) * 64;
                #pragma unroll
                for (int d = 0; d < DD; d++) {
                    u64t wp[2][4];
                    #pragma unroll
                    for (int g = 0; g < 4; g++) {
                        u64t wv = lds64(&sW1T[d * G1 + g * H1 + u01]);
                        float wl, wh; upk(wv, wl, wh);
                        wp[0][g] = pk2(wl, wl); wp[1][g] = pk2(wh, wh);
                    }
                    #pragma unroll
                    for (int p = 0; p < 4; p++) {
                        u64t xv = lds64(&bufn[d * XS + 2 * p]);
                        #pragma unroll
                        for (int g = 0; g < 4; g++) {
                            a1[0][g][p] = fma2(wp[0][g], xv, a1[0][g][p]);
                            a1[1][g][p] = fma2(wp[1][g], xv, a1[1][g][p]);
                        }
                    }
                }
            }
            __syncwarp();                      // h2 RAW for next iter's L2-rec
        }

        // ================= head: dense(16)+relu -> dot(16)+sigmoid =============
        if (lane < TB) {
            const int b = lane;
            float hv[H2];
            #pragma unroll
            for (int k = 0; k < H2; k++) hv[k] = sH2w[k * HS2 + b];
            float o = __ldg(&bo[0]);
            #pragma unroll
            for (int j = 0; j < 16; j++) {
                float s = __ldg(&bd[j]);
                #pragma unroll
                for (int k = 0; k < H2; k++) s += hv[k] * __ldg(&Wd[j * H2 + k]);
                o += fmaxf(s, 0.0f) * __ldg(&Wo[j]);
            }
            out[tau * TB + b] = sigx(o);
        }
        __syncwarp();                          // head reads done before next-task zeroing
    }
}

extern "C" void kernel_launch(void* const* d_in, const int* in_sizes, int n_in,
                              void* d_out, int out_size) {
    const float* x    = (const float*)d_in[0];
    const float* Wih1 = (const float*)d_in[1];
    const float* Whh1 = (const float*)d_in[2];
    const float* bih1 = (const float*)d_in[3];
    const float* bhh1 = (const float*)d_in[4];
    const float* Wih2 = (const float*)d_in[5];
    const float* Whh2 = (const float*)d_in[6];
    const float* bih2 = (const float*)d_in[7];
    const float* bhh2 = (const float*)d_in[8];
    const float* Wd   = (const float*)d_in[9];
    const float* bd   = (const float*)d_in[10];
    const float* Wo   = (const float*)d_in[11];
    const float* bo   = (const float*)d_in[12];
    float* out = (float*)d_out;

    static bool attr_set = false;
    if (!attr_set) {
        cudaFuncSetAttribute(momentum_lstm_kernel,
                             cudaFuncAttributeMaxDynamicSharedMemorySize, SMEM_BYTES);
        attr_set = true;
    }

    momentum_lstm_kernel<<<GRID, NT, SMEM_BYTES>>>(
        x, Wih1, Whh1, bih1, bhh1, Wih2, Whh2, bih2, bhh2, Wd, bd, Wo, bo, out);
}

// round 16
// speedup vs baseline: 1.0160x; 1.0160x over previous
#include <cuda_runtime.h>
#include <cuda_bf16.h>

// MomentumLSTM v15: v13 base (best 2073us) + ONE isolated micro-win:
// pre-duplicated (b,b) bias pairs in SMEM -> accumulator init is pure broadcast
// LDS.64 (16 issues/step instead of ~40). Everything else byte-identical to v13:
//   L1 gates -> sync -> [pw-L1 || L2-rec] -> sync -> L2-input -> pw-L2 -> sync

#define BATCH  32768
#define TT     60
#define DD     7
#define H1     64
#define G1     256
#define H2     32
#define G2     128
#define NT     512
#define GRID   152
#define TB     8                 // batches per warp-task
#define NTASKS (BATCH / TB)      // 4096
#define WSLOTS (GRID * 16)       // 2432
#define HS1    10                // even stride: [64][10] per-warp h1 slab
#define HS2    10                // [32][10]
#define XS     8                 // [7][8]

// SMEM float offsets
#define OFF_W1T 0                // [71][256] rows 0..6 x-w, 7..70 h-w (i/f/o pre-scaled 0.5)
#define OFF_W2T 18176            // [96][128]
#define OFF_B1D 30464            // [512] duplicated (b,b) pairs, index 2*(g*H1+u)
#define OFF_B2D 30976            // [256] duplicated
#define OFF_H1  31232            // 16 x 640
#define OFF_H2  41472            // 16 x 320
#define OFF_X   46592            // 16 x 64
#define SMEM_FLOATS 47616
#define SMEM_BYTES  (SMEM_FLOATS * 4)   // 190464

typedef unsigned long long u64t;

__device__ __forceinline__ u64t pk2(float a, float b) {
    u64t r; asm("mov.b64 %0, {%1, %2};" : "=l"(r) : "f"(a), "f"(b)); return r;
}
__device__ __forceinline__ void upk(u64t v, float& lo, float& hi) {
    asm("mov.b64 {%0, %1}, %2;" : "=f"(lo), "=f"(hi) : "l"(v));
}
__device__ __forceinline__ u64t fma2(u64t a, u64t b, u64t c) {
    u64t d; asm("fma.rn.f32x2 %0, %1, %2, %3;" : "=l"(d) : "l"(a), "l"(b), "l"(c)); return d;
}
__device__ __forceinline__ u64t lds64(const float* p) {
    return *reinterpret_cast<const u64t*>(p);
}
__device__ __forceinline__ void sts64(float* p, u64t v) {
    *reinterpret_cast<u64t*>(p) = v;
}
__device__ __forceinline__ float tanha(float x) {
    float y; asm("tanh.approx.f32 %0, %1;" : "=f"(y) : "f"(x)); return y;
}
// acc already holds x/2 (weights pre-scaled): sigmoid(x) = 0.5*tanh(x/2)+0.5
__device__ __forceinline__ float sig_h(float halfx) {
    return fmaf(0.5f, tanha(halfx), 0.5f);
}
__device__ __forceinline__ float sigx(float x) {   // exact, output only
    return __fdividef(1.0f, 1.0f + __expf(-x));
}

__global__ void __launch_bounds__(NT, 1)
momentum_lstm_kernel(const float* __restrict__ x,
                     const float* __restrict__ Wih1, const float* __restrict__ Whh1,
                     const float* __restrict__ bih1, const float* __restrict__ bhh1,
                     const float* __restrict__ Wih2, const float* __restrict__ Whh2,
                     const float* __restrict__ bih2, const float* __restrict__ bhh2,
                     const float* __restrict__ Wd,  const float* __restrict__ bd,
                     const float* __restrict__ Wo,  const float* __restrict__ bo,
                     float* __restrict__ out)
{
    extern __shared__ float sm[];
    float* sW1T = sm + OFF_W1T;
    float* sW2T = sm + OFF_W2T;
    float* sB1d = sm + OFF_B1D;
    float* sB2d = sm + OFF_B2D;

    const int tid  = threadIdx.x;
    const int lane = tid & 31;
    const int wid  = tid >> 5;

    float* sH1w = sm + OFF_H1 + wid * (H1 * HS1);
    float* sH2w = sm + OFF_H2 + wid * (H2 * HS2);
    float* sXw  = sm + OFF_X  + wid * 64;

    // ---------------- staging: transpose + pre-scale i/f/o rows by 0.5 ----------------
    for (int i = tid; i < DD * G1; i += NT) {
        int d = i >> 8, g = i & 255;
        float s = ((g >> 6) == 2) ? 1.0f : 0.5f;       // gate order i,f,g,o
        sW1T[d * G1 + g] = s * Wih1[g * DD + d];
    }
    for (int i = tid; i < H1 * G1; i += NT) {
        int k = i >> 8, g = i & 255;
        float s = ((g >> 6) == 2) ? 1.0f : 0.5f;
        sW1T[(DD + k) * G1 + g] = s * Whh1[g * H1 + k];
    }
    for (int i = tid; i < (H1 + H2) * G2; i += NT) {
        int k = i >> 7, g = i & 127;
        float s = ((g >> 5) == 2) ? 1.0f : 0.5f;
        sW2T[i] = s * ((k < H1) ? Wih2[g * H1 + k] : Whh2[g * H2 + (k - H1)]);
    }
    if (tid < G1) {
        float s = ((tid >> 6) == 2) ? 1.0f : 0.5f;
        float b = s * (bih1[tid] + bhh1[tid]);
        sB1d[2 * tid] = b; sB1d[2 * tid + 1] = b;      // duplicated (b,b) pair
    }
    if (tid < G2) {
        float s = ((tid >> 5) == 2) ? 1.0f : 0.5f;
        float b = s * (bih2[tid] + bhh2[tid]);
        sB2d[2 * tid] = b; sB2d[2 * tid + 1] = b;
    }
    __syncthreads();

    // ---------------- warp-local tilings ----------------
    const int u01 = 2 * lane;               // layer1: lanes span 64 units
    const int u02 = 2 * (lane & 15);        // layer2: 16 lanes span 32 units
    const int bh2 = (lane >> 4) * 4;        // layer2: half-warp batch split (4 each)

    const int gw = wid * GRID + blockIdx.x;   // interleaved task id

    for (int tau = gw; tau < NTASKS; tau += WSLOTS) {
        const float* xg = x + (size_t)tau * TB * (TT * DD);

        // zero h2 slab (L2-recurrent loop is branch-free, reads zeros at t=0)
        for (int i = lane; i < H2 * HS2; i += 32) sH2w[i] = 0.0f;
        __syncwarp();

        float c1[2][TB];
        #pragma unroll
        for (int u = 0; u < 2; u++)
            #pragma unroll
            for (int b = 0; b < TB; b++) c1[u][b] = 0.0f;
        float c2[2][4];
        #pragma unroll
        for (int u = 0; u < 2; u++)
            #pragma unroll
            for (int b = 0; b < 4; b++) c2[u][b] = 0.0f;

        // prefetch x(t=0)
        float xr[2];
        #pragma unroll
        for (int j = 0; j < 2; j++) {
            int idx = 32 * j + lane;
            if (idx < DD * TB) {
                int b = idx / DD, d = idx - b * DD;
                xr[j] = xg[b * (TT * DD) + d];
            }
        }

        for (int t = 0; t < TT; t++) {
            // store x(t); prefetch x(t+1)
            #pragma unroll
            for (int j = 0; j < 2; j++) {
                int idx = 32 * j + lane;
                if (idx < DD * TB) {
                    int b = idx / DD, d = idx - b * DD;
                    sXw[d * XS + b] = xr[j];
                }
            }
            __syncwarp();
            if (t + 1 < TT) {
                #pragma unroll
                for (int j = 0; j < 2; j++) {
                    int idx = 32 * j + lane;
                    if (idx < DD * TB) {
                        int b = idx / DD, d = idx - b * DD;
                        xr[j] = xg[b * (TT * DD) + (t + 1) * DD + d];
                    }
                }
            }

            // ================= layer 1 gates =================
            u64t a1[2][4][4];
            #pragma unroll
            for (int g = 0; g < 4; g++) {
                u64t plo = lds64(&sB1d[2 * (g * H1 + u01)]);       // (b,b) broadcast
                u64t phi = lds64(&sB1d[2 * (g * H1 + u01 + 1)]);
                #pragma unroll
                for (int p = 0; p < 4; p++) { a1[0][g][p] = plo; a1[1][g][p] = phi; }
            }
            #pragma unroll
            for (int d = 0; d < DD; d++) {
                u64t wp[2][4];
                #pragma unroll
                for (int g = 0; g < 4; g++) {
                    u64t wv = lds64(&sW1T[d * G1 + g * H1 + u01]);
                    float wl, wh; upk(wv, wl, wh);
                    wp[0][g] = pk2(wl, wl); wp[1][g] = pk2(wh, wh);
                }
                #pragma unroll
                for (int p = 0; p < 4; p++) {
                    u64t xv = lds64(&sXw[d * XS + 2 * p]);
                    #pragma unroll
                    for (int g = 0; g < 4; g++) {
                        a1[0][g][p] = fma2(wp[0][g], xv, a1[0][g][p]);
                        a1[1][g][p] = fma2(wp[1][g], xv, a1[1][g][p]);
                    }
                }
            }
            if (t) {                               // h1(t-1) == 0 at t==0
                #pragma unroll 2
                for (int k = 0; k < H1; k++) {
                    u64t wp[2][4];
                    #pragma unroll
                    for (int g = 0; g < 4; g++) {
                        u64t wv = lds64(&sW1T[(DD + k) * G1 + g * H1 + u01]);
                        float wl, wh; upk(wv, wl, wh);
                        wp[0][g] = pk2(wl, wl); wp[1][g] = pk2(wh, wh);
                    }
                    #pragma unroll
                    for (int p = 0; p < 4; p++) {
                        u64t hv = lds64(&sH1w[k * HS1 + 2 * p]);
                        #pragma unroll
                        for (int g = 0; g < 4; g++) {
                            a1[0][g][p] = fma2(wp[0][g], hv, a1[0][g][p]);
                            a1[1][g][p] = fma2(wp[1][g], hv, a1[1][g][p]);
                        }
                    }
                }
            }
            __syncwarp();                      // WAR on old h1

            // ====== FUSED region: pointwise-L1 (MUFU) || layer2-recurrent (FMA) ======
            u64t a2[2][4][2];
            #pragma unroll
            for (int g = 0; g < 4; g++) {
                u64t plo = lds64(&sB2d[2 * (g * H2 + u02)]);
                u64t phi = lds64(&sB2d[2 * (g * H2 + u02 + 1)]);
                #pragma unroll
                for (int p = 0; p < 2; p++) { a2[0][g][p] = plo; a2[1][g][p] = phi; }
            }
            // pointwise layer1 + write new h1 (MUFU-heavy)
            #pragma unroll
            for (int u = 0; u < 2; u++) {
                #pragma unroll
                for (int p = 0; p < 4; p++) {
                    float gi[2], gf[2], gg[2], go[2], hh[2];
                    upk(a1[u][0][p], gi[0], gi[1]);
                    upk(a1[u][1][p], gf[0], gf[1]);
                    upk(a1[u][2][p], gg[0], gg[1]);
                    upk(a1[u][3][p], go[0], go[1]);
                    #pragma unroll
                    for (int s = 0; s < 2; s++) {
                        float ii = sig_h(gi[s]);
                        float ff = sig_h(gf[s]);
                        float g_ = tanha(gg[s]);
                        float oo = sig_h(go[s]);
                        float cc = ff * c1[u][2 * p + s] + ii * g_;
                        c1[u][2 * p + s] = cc;
                        hh[s] = oo * tanha(cc);
                    }
                    sts64(&sH1w[(u01 + u) * HS1 + 2 * p], pk2(hh[0], hh[1]));
                }
            }
            // layer2 recurrent gates (reads OLD h2 — independent of pointwise-L1)
            #pragma unroll 4
            for (int k = 0; k < H2; k++) {
                u64t wp[2][4];
                #pragma unroll
                for (int g = 0; g < 4; g++) {
                    u64t wv = lds64(&sW2T[(H1 + k) * G2 + g * H2 + u02]);
                    float wl, wh; upk(wv, wl, wh);
                    wp[0][g] = pk2(wl, wl); wp[1][g] = pk2(wh, wh);
                }
                #pragma unroll
                for (int p = 0; p < 2; p++) {
                    u64t hv = lds64(&sH2w[k * HS2 + bh2 + 2 * p]);
                    #pragma unroll
                    for (int g = 0; g < 4; g++) {
                        a2[0][g][p] = fma2(wp[0][g], hv, a2[0][g][p]);
                        a2[1][g][p] = fma2(wp[1][g], hv, a2[1][g][p]);
                    }
                }
            }
            __syncwarp();    // new h1 visible (RAW); all old-h2 reads retired (WAR)

            // ================= layer2 input gates (new h1) =================
            #pragma unroll 4
            for (int k = 0; k < H1; k++) {
                u64t wp[2][4];
                #pragma unroll
                for (int g = 0; g < 4; g++) {
                    u64t wv = lds64(&sW2T[k * G2 + g * H2 + u02]);
                    float wl, wh; upk(wv, wl, wh);
                    wp[0][g] = pk2(wl, wl); wp[1][g] = pk2(wh, wh);
                }
                #pragma unroll
                for (int p = 0; p < 2; p++) {
                    u64t hv = lds64(&sH1w[k * HS1 + bh2 + 2 * p]);
                    #pragma unroll
                    for (int g = 0; g < 4; g++) {
                        a2[0][g][p] = fma2(wp[0][g], hv, a2[0][g][p]);
                        a2[1][g][p] = fma2(wp[1][g], hv, a2[1][g][p]);
                    }
                }
            }

            // pointwise layer2 + write new h2
            #pragma unroll
            for (int u = 0; u < 2; u++) {
                #pragma unroll
                for (int p = 0; p < 2; p++) {
                    float gi[2], gf[2], gg[2], go[2], hh[2];
                    upk(a2[u][0][p], gi[0], gi[1]);
                    upk(a2[u][1][p], gf[0], gf[1]);
                    upk(a2[u][2][p], gg[0], gg[1]);
                    upk(a2[u][3][p], go[0], go[1]);
                    #pragma unroll
                    for (int s = 0; s < 2; s++) {
                        float ii = sig_h(gi[s]);
                        float ff = sig_h(gf[s]);
                        float g_ = tanha(gg[s]);
                        float oo = sig_h(go[s]);
                        float cc = ff * c2[u][2 * p + s] + ii * g_;
                        c2[u][2 * p + s] = cc;
                        hh[s] = oo * tanha(cc);
                    }
                    sts64(&sH2w[(u02 + u) * HS2 + bh2 + 2 * p], pk2(hh[0], hh[1]));
                }
            }
            __syncwarp();                      // new h2 visible
        }

        // ================= head: dense(16)+relu -> dot(16)+sigmoid =============
        if (lane < TB) {
            const int b = lane;
            float hv[H2];
            #pragma unroll
            for (int k = 0; k < H2; k++) hv[k] = sH2w[k * HS2 + b];
            float o = __ldg(&bo[0]);
            #pragma unroll
            for (int j = 0; j < 16; j++) {
                float s = __ldg(&bd[j]);
                #pragma unroll
                for (int k = 0; k < H2; k++) s += hv[k] * __ldg(&Wd[j * H2 + k]);
                o += fmaxf(s, 0.0f) * __ldg(&Wo[j]);
            }
            out[tau * TB + b] = sigx(o);
        }
        __syncwarp();                          // head reads done before next-task zeroing
    }
}

extern "C" void kernel_launch(void* const* d_in, const int* in_sizes, int n_in,
                              void* d_out, int out_size) {
    const float* x    = (const float*)d_in[0];
    const float* Wih1 = (const float*)d_in[1];
    const float* Whh1 = (const float*)d_in[2];
    const float* bih1 = (const float*)d_in[3];
    const float* bhh1 = (const float*)d_in[4];
    const float* Wih2 = (const float*)d_in[5];
    const float* Whh2 = (const float*)d_in[6];
    const float* bih2 = (const float*)d_in[7];
    const float* bhh2 = (const float*)d_in[8];
    const float* Wd   = (const float*)d_in[9];
    const float* bd   = (const float*)d_in[10];
    const float* Wo   = (const float*)d_in[11];
    const float* bo   = (const float*)d_in[12];
    float* out = (float*)d_out;

    static bool attr_set = false;
    if (!attr_set) {
        cudaFuncSetAttribute(momentum_lstm_kernel,
                             cudaFuncAttributeMaxDynamicSharedMemorySize, SMEM_BYTES);
        attr_set = true;
    }

    momentum_lstm_kernel<<<GRID, NT, SMEM_BYTES>>>(
        x, Wih1, Whh1, bih1, bhh1, Wih2, Whh2, bih2, bhh2, Wd, bd, Wo, bo, out);
}